// round 6
// baseline (speedup 1.0000x reference)
#include <cuda_runtime.h>
#include <stdint.h>

// ---------------------------------------------------------------------------
// Binarized CNN (BinaryNet semantics, sign(0)=0 => ternary after conv2):
//   conv1: [B,1,15,15] -> [B,4,7,7]  (3x3 stride2, VALID), hardtanh
//   conv2: -> [B,8,3,3], conv3: -> [B,16,1,1], fc1: 16->8, fc2: 8->1
// negbit convention: bit = 1 <=> value negative (fp32 sign bit).
// Values after conv2 tracked as (negbit, nonzero) pairs.
//
// Single fused kernel: each CTA rebuilds all packed weight masks + the conv1
// LUT in shared memory (weights are ~1.6K floats, L2-hot), then runs
// warp-cooperative coalesced binarization + 1 lane = 1 sample compute.
// ---------------------------------------------------------------------------

__global__ __launch_bounds__(256)
void net_kernel(const float* __restrict__ x,
                const float* __restrict__ w1,
                const float* __restrict__ w2,
                const float* __restrict__ w3,
                const float* __restrict__ wfc1,
                const float* __restrict__ wfc2,
                float* __restrict__ out, int n)
{
    __shared__ uint32_t           bitbuf[8][225]; // per-warp: 32 samples x 225 bits
    __shared__ unsigned char      lut[512];       // conv1: 9-bit window -> 4 negbits
    __shared__ uint32_t           sW1[4];         // 9-bit negbits, bit = ky*3+kx
    __shared__ unsigned long long sW2[8];         // 36-bit, bit = (ky*3+kx)*4 + c
    __shared__ unsigned long long sW3lo[16];      // bits 0..63 of idx = c*9 + p
    __shared__ uint32_t           sW3hi[16];      // bits 64..71
    __shared__ uint32_t           sWF1[8];        // 16-bit negbits
    __shared__ uint32_t           sWF2;           // 8-bit negbits

    const int t = threadIdx.x;

    // ---- prep stage A: pack weight masks (disjoint thread ranges) ----
    if (t < 4) {                        // conv1 masks
        uint32_t m = 0;
#pragma unroll
        for (int i = 0; i < 9; i++)
            m |= (__float_as_uint(__ldg(w1 + t * 9 + i)) >> 31) << i;
        sW1[t] = m;
    }
    if (t >= 8 && t < 16) {             // conv2: bit (p*4 + c)
        int k = t - 8;
        unsigned long long m = 0;
#pragma unroll
        for (int c = 0; c < 4; c++)
#pragma unroll
            for (int p = 0; p < 9; p++) {
                unsigned long long b =
                    (unsigned long long)(__float_as_uint(__ldg(w2 + k * 36 + c * 9 + p)) >> 31);
                m |= b << (p * 4 + c);
            }
        sW2[k] = m;
    }
    if (t >= 32 && t < 48) {            // conv3: bit idx = c*9 + p
        int j = t - 32;
        unsigned long long lo = 0; uint32_t hi = 0;
#pragma unroll
        for (int c = 0; c < 8; c++)
#pragma unroll
            for (int p = 0; p < 9; p++) {
                int idx = c * 9 + p;
                uint32_t b = __float_as_uint(__ldg(w3 + j * 72 + c * 9 + p)) >> 31;
                if (idx < 64) lo |= (unsigned long long)b << idx;
                else          hi |= b << (idx - 64);
            }
        sW3lo[j] = lo; sW3hi[j] = hi;
    }
    if (t >= 64 && t < 72) {            // fc1: [8][16]
        int o = t - 64;
        uint32_t m = 0;
#pragma unroll
        for (int i = 0; i < 16; i++)
            m |= (__float_as_uint(__ldg(wfc1 + o * 16 + i)) >> 31) << i;
        sWF1[o] = m;
    }
    if (t == 100) {                     // fc2: [1][8]
        uint32_t m = 0;
#pragma unroll
        for (int i = 0; i < 8; i++)
            m |= (__float_as_uint(__ldg(wfc2 + i)) >> 31) << i;
        sWF2 = m;
    }
    __syncthreads();

    // ---- prep stage B: conv1 LUT (2 entries per thread, reads sW1) ----
#pragma unroll
    for (int e = t; e < 512; e += 256) {
        uint32_t lutv = 0;
#pragma unroll
        for (int k = 0; k < 4; k++) {
            int mism = __popc(((uint32_t)e ^ sW1[k]) & 0x1FF);
            lutv |= (uint32_t)(mism >= 5) << k;   // sum = 9 - 2*mism < 0
        }
        lut[e] = (unsigned char)lutv;
    }
    __syncthreads();

    const int w  = t >> 5;
    const int l  = t & 31;
    const int s0 = blockIdx.x * 256 + w * 32;   // first sample of this warp
    if (s0 >= n) return;

    // ---- phase 1: coalesced streaming load + ballot binarize -> smem ----
    const float* base = x + (size_t)s0 * 225;
    const bool full = (s0 + 32 <= n);
    const long long lim = (long long)(n - s0) * 225;  // valid flat elems
#pragma unroll 15
    for (int i = 0; i < 225; i++) {
        int idx = i * 32 + l;
        float v = (full || idx < lim) ? __ldcs(base + idx) : 1.0f;
        uint32_t b = __ballot_sync(0xFFFFFFFFu, (__float_as_uint(v) >> 31) & 1u);
        if (l == 0) bitbuf[w][i] = b;
    }
    __syncwarp();

    int s = s0 + l;
    if (s >= n) return;

    // ---- phase 2: extract my 225-bit sample string (conflict-free LDS) ----
    uint32_t W[8];
    {
        int bitoff = l * 225;
        int wi = bitoff >> 5;
#pragma unroll
        for (int k = 0; k < 8; k++) W[k] = bitbuf[w][wi + k];
        int sh = bitoff & 31;
        uint32_t v[8];
#pragma unroll
        for (int k = 0; k < 7; k++) v[k] = __funnelshift_r(W[k], W[k + 1], sh);
        v[7] = W[7] >> sh;
#pragma unroll
        for (int k = 0; k < 8; k++) W[k] = v[k];   // W = aligned 225-bit string
    }

    // 15 rows of 15 sign bits
    uint32_t rows[15];
#pragma unroll
    for (int y = 0; y < 15; y++) {
        int b = 15 * y;
        int i = b >> 5, sh = b & 31;
        uint32_t hi2 = (i < 7) ? W[i + 1] : 0u;
        rows[y] = __funnelshift_r(W[i], hi2, sh) & 0x7FFFu;
    }

    // ---- conv1 (LUT): nibble per position (bit 4*ox + k) ----
    uint32_t b1r[7];
#pragma unroll
    for (int oy = 0; oy < 7; oy++) {
        uint32_t r0 = rows[2 * oy], r1 = rows[2 * oy + 1], r2 = rows[2 * oy + 2];
        uint32_t acc = 0;
#pragma unroll
        for (int ox = 0; ox < 7; ox++) {
            uint32_t win = ((r0 >> (2 * ox)) & 7)
                         | (((r1 >> (2 * ox)) & 7) << 3)
                         | (((r2 >> (2 * ox)) & 7) << 6);
            acc |= (uint32_t)lut[win] << (4 * ox);
        }
        b1r[oy] = acc;
    }

    // ---- conv2: 36-bit XNOR window, ternary output (negbit, nonzero) ----
    unsigned long long b2lo = 0, nzlo = 0;
    uint32_t b2hi = 0, nzhi = 0;
#pragma unroll
    for (int oy = 0; oy < 3; oy++) {
#pragma unroll
        for (int ox = 0; ox < 3; ox++) {
            uint32_t q0 = (b1r[2 * oy]     >> (8 * ox)) & 0xFFF;
            uint32_t q1 = (b1r[2 * oy + 1] >> (8 * ox)) & 0xFFF;
            uint32_t q2 = (b1r[2 * oy + 2] >> (8 * ox)) & 0xFFF;
            unsigned long long win =
                (unsigned long long)(q0 | (q1 << 12)) | ((unsigned long long)q2 << 24);
#pragma unroll
            for (int k = 0; k < 8; k++) {
                int mism = __popcll(win ^ sW2[k]);   // sum = 36 - 2*mism
                int idx = k * 9 + oy * 3 + ox;
                unsigned long long sb = (unsigned long long)(mism > 18);
                unsigned long long zb = (unsigned long long)(mism != 18);
                if (idx < 64) { b2lo |= sb << idx;           nzlo |= zb << idx; }
                else          { b2hi |= (uint32_t)sb << (idx - 64);
                                nzhi |= (uint32_t)zb << (idx - 64); }
            }
        }
    }

    // ---- conv3: 72 ternary inputs, 16 outputs ----
    int ztot = __popcll(nzlo) + __popc(nzhi);
    uint32_t b3 = 0, nz3 = 0;
#pragma unroll
    for (int j = 0; j < 16; j++) {
        int m = __popcll(nzlo & ~(b2lo ^ sW3lo[j]))
              + __popc((nzhi & ~(b2hi ^ sW3hi[j])) & 0xFF);
        int sum = 2 * m - ztot;
        b3  |= (uint32_t)(sum < 0)  << j;
        nz3 |= (uint32_t)(sum != 0) << j;
    }

    // ---- fc1: 16 ternary inputs, 8 outputs ----
    int z3 = __popc(nz3);
    uint32_t b4 = 0, nz4 = 0;
#pragma unroll
    for (int o = 0; o < 8; o++) {
        int m = __popc((nz3 & ~(b3 ^ sWF1[o])) & 0xFFFF);
        int sum = 2 * m - z3;
        b4  |= (uint32_t)(sum < 0)  << o;
        nz4 |= (uint32_t)(sum != 0) << o;
    }

    // ---- fc2: raw integer sum as float (streaming store) ----
    int m = __popc((nz4 & ~(b4 ^ sWF2)) & 0xFF);
    __stcs(out + s, (float)(2 * m - __popc(nz4)));
}

// ---------------------------------------------------------------------------
// Inputs (metadata order): x, w1, w2, w3, wfc1, wfc2
// ---------------------------------------------------------------------------
extern "C" void kernel_launch(void* const* d_in, const int* in_sizes, int n_in,
                              void* d_out, int out_size)
{
    const float* x    = (const float*)d_in[0];
    const float* w1   = (const float*)d_in[1];
    const float* w2   = (const float*)d_in[2];
    const float* w3   = (const float*)d_in[3];
    const float* wfc1 = (const float*)d_in[4];
    const float* wfc2 = (const float*)d_in[5];
    int n = in_sizes[0] / 225;

    net_kernel<<<(n + 255) / 256, 256>>>(x, w1, w2, w3, wfc1, wfc2,
                                         (float*)d_out, n);
}

// round 11
// speedup vs baseline: 1.3157x; 1.3157x over previous
#include <cuda_runtime.h>
#include <stdint.h>

// ---------------------------------------------------------------------------
// Binarized CNN (BinaryNet semantics, sign(0)=0 => ternary after conv2):
//   conv1: [B,1,15,15] -> [B,4,7,7]  (3x3 stride2, VALID), hardtanh
//   conv2: -> [B,8,3,3], conv3: -> [B,16,1,1], fc1: 16->8, fc2: 8->1
// negbit convention: bit = 1 <=> value negative (fp32 sign bit).
// Values after conv2 tracked as (negbit, nonzero) pairs.
//
// Single fused kernel. Phase 1 uses vectorized float4 loads: each lane builds
// a sign nibble, 3 shfl_xor rounds OR-combine 8 lanes' nibbles into one
// 32-bit word of the per-warp bit buffer. Compute: 1 lane = 1 sample.
// ---------------------------------------------------------------------------

__global__ __launch_bounds__(256)
void net_kernel(const float* __restrict__ x,
                const float* __restrict__ w1,
                const float* __restrict__ w2,
                const float* __restrict__ w3,
                const float* __restrict__ wfc1,
                const float* __restrict__ wfc2,
                float* __restrict__ out, int n)
{
    __shared__ uint32_t           bitbuf[8][225]; // per-warp: 32 samples x 225 bits
    __shared__ unsigned char      lut[512];       // conv1: 9-bit window -> 4 negbits
    __shared__ uint32_t           sW1[4];         // 9-bit negbits, bit = ky*3+kx
    __shared__ unsigned long long sW2[8];         // 36-bit, bit = (ky*3+kx)*4 + c
    __shared__ unsigned long long sW3lo[16];      // bits 0..63 of idx = c*9 + p
    __shared__ uint32_t           sW3hi[16];      // bits 64..71
    __shared__ uint32_t           sWF1[8];        // 16-bit negbits
    __shared__ uint32_t           sWF2;           // 8-bit negbits

    const int t = threadIdx.x;

    // ---- prep stage A: pack weight masks (disjoint thread ranges) ----
    if (t < 4) {                        // conv1 masks
        uint32_t m = 0;
#pragma unroll
        for (int i = 0; i < 9; i++)
            m |= (__float_as_uint(__ldg(w1 + t * 9 + i)) >> 31) << i;
        sW1[t] = m;
    }
    if (t >= 8 && t < 16) {             // conv2: bit (p*4 + c)
        int k = t - 8;
        unsigned long long m = 0;
#pragma unroll
        for (int c = 0; c < 4; c++)
#pragma unroll
            for (int p = 0; p < 9; p++) {
                unsigned long long b =
                    (unsigned long long)(__float_as_uint(__ldg(w2 + k * 36 + c * 9 + p)) >> 31);
                m |= b << (p * 4 + c);
            }
        sW2[k] = m;
    }
    if (t >= 32 && t < 48) {            // conv3: bit idx = c*9 + p
        int j = t - 32;
        unsigned long long lo = 0; uint32_t hi = 0;
#pragma unroll
        for (int c = 0; c < 8; c++)
#pragma unroll
            for (int p = 0; p < 9; p++) {
                int idx = c * 9 + p;
                uint32_t b = __float_as_uint(__ldg(w3 + j * 72 + c * 9 + p)) >> 31;
                if (idx < 64) lo |= (unsigned long long)b << idx;
                else          hi |= b << (idx - 64);
            }
        sW3lo[j] = lo; sW3hi[j] = hi;
    }
    if (t >= 64 && t < 72) {            // fc1: [8][16]
        int o = t - 64;
        uint32_t m = 0;
#pragma unroll
        for (int i = 0; i < 16; i++)
            m |= (__float_as_uint(__ldg(wfc1 + o * 16 + i)) >> 31) << i;
        sWF1[o] = m;
    }
    if (t == 100) {                     // fc2: [1][8]
        uint32_t m = 0;
#pragma unroll
        for (int i = 0; i < 8; i++)
            m |= (__float_as_uint(__ldg(wfc2 + i)) >> 31) << i;
        sWF2 = m;
    }
    __syncthreads();

    // ---- prep stage B: conv1 LUT (2 entries per thread, reads sW1) ----
#pragma unroll
    for (int e = t; e < 512; e += 256) {
        uint32_t lutv = 0;
#pragma unroll
        for (int k = 0; k < 4; k++) {
            int mism = __popc(((uint32_t)e ^ sW1[k]) & 0x1FF);
            lutv |= (uint32_t)(mism >= 5) << k;   // sum = 9 - 2*mism < 0
        }
        lut[e] = (unsigned char)lutv;
    }
    __syncthreads();

    const int w  = t >> 5;
    const int l  = t & 31;
    const int s0 = blockIdx.x * 256 + w * 32;   // first sample of this warp
    if (s0 >= n) return;

    // ---- phase 1: binarize 32 samples (7200 floats) -> 225-word bit buffer ----
    const float* base = x + (size_t)s0 * 225;
    const bool full = (s0 + 32 <= n);

    if (full) {
        // vectorized: lane l, iter i handles float4 k = i*32+l, i.e. global
        // elements 4k..4k+3 -> nibble slot (l&7) of word i*4 + (l>>3).
        const float4* basev = (const float4*)base;
        const int sh4 = (l & 7) * 4;
#pragma unroll 8
        for (int i = 0; i < 56; i++) {
            float4 f = __ldcs(basev + i * 32 + l);
            uint32_t nib = ( __float_as_uint(f.x) >> 31)
                         | ((__float_as_uint(f.y) >> 31) << 1)
                         | ((__float_as_uint(f.z) >> 31) << 2)
                         | ((__float_as_uint(f.w) >> 31) << 3);
            uint32_t v = nib << sh4;
            v |= __shfl_xor_sync(0xFFFFFFFFu, v, 1);
            v |= __shfl_xor_sync(0xFFFFFFFFu, v, 2);
            v |= __shfl_xor_sync(0xFFFFFFFFu, v, 4);
            if ((l & 7) == 0) bitbuf[w][i * 4 + (l >> 3)] = v;
        }
        // tail: elements 7168..7199 -> word 224
        float vf = __ldcs(base + 7168 + l);
        uint32_t b = __ballot_sync(0xFFFFFFFFu, __float_as_uint(vf) >> 31);
        if (l == 0) bitbuf[w][224] = b;
    } else {
        const long long lim = (long long)(n - s0) * 225;  // valid flat elems
        for (int i = 0; i < 225; i++) {
            int idx = i * 32 + l;
            float v = (idx < lim) ? __ldcs(base + idx) : 1.0f;
            uint32_t b = __ballot_sync(0xFFFFFFFFu, (__float_as_uint(v) >> 31) & 1u);
            if (l == 0) bitbuf[w][i] = b;
        }
    }
    __syncwarp();

    int s = s0 + l;
    if (s >= n) return;

    // ---- phase 2: extract my 225-bit sample string (conflict-free LDS) ----
    uint32_t W[8];
    {
        int bitoff = l * 225;
        int wi = bitoff >> 5;
#pragma unroll
        for (int k = 0; k < 8; k++) W[k] = bitbuf[w][wi + k];
        int sh = bitoff & 31;
        uint32_t v[8];
#pragma unroll
        for (int k = 0; k < 7; k++) v[k] = __funnelshift_r(W[k], W[k + 1], sh);
        v[7] = W[7] >> sh;
#pragma unroll
        for (int k = 0; k < 8; k++) W[k] = v[k];   // W = aligned 225-bit string
    }

    // 15 rows of 15 sign bits
    uint32_t rows[15];
#pragma unroll
    for (int y = 0; y < 15; y++) {
        int b = 15 * y;
        int i = b >> 5, sh = b & 31;
        uint32_t hi2 = (i < 7) ? W[i + 1] : 0u;
        rows[y] = __funnelshift_r(W[i], hi2, sh) & 0x7FFFu;
    }

    // ---- conv1 (LUT): nibble per position (bit 4*ox + k) ----
    uint32_t b1r[7];
#pragma unroll
    for (int oy = 0; oy < 7; oy++) {
        uint32_t r0 = rows[2 * oy], r1 = rows[2 * oy + 1], r2 = rows[2 * oy + 2];
        uint32_t acc = 0;
#pragma unroll
        for (int ox = 0; ox < 7; ox++) {
            uint32_t win = ((r0 >> (2 * ox)) & 7)
                         | (((r1 >> (2 * ox)) & 7) << 3)
                         | (((r2 >> (2 * ox)) & 7) << 6);
            acc |= (uint32_t)lut[win] << (4 * ox);
        }
        b1r[oy] = acc;
    }

    // ---- conv2: 36-bit XNOR window; per-filter 9-bit (negbit, nonzero) ----
    uint32_t m8[8], z8[8];
#pragma unroll
    for (int k = 0; k < 8; k++) { m8[k] = 0; z8[k] = 0; }
#pragma unroll
    for (int oy = 0; oy < 3; oy++) {
#pragma unroll
        for (int ox = 0; ox < 3; ox++) {
            uint32_t q0 = (b1r[2 * oy]     >> (8 * ox)) & 0xFFF;
            uint32_t q1 = (b1r[2 * oy + 1] >> (8 * ox)) & 0xFFF;
            uint32_t q2 = (b1r[2 * oy + 2] >> (8 * ox)) & 0xFFF;
            unsigned long long win =
                (unsigned long long)(q0 | (q1 << 12)) | ((unsigned long long)q2 << 24);
            const int pos = oy * 3 + ox;
#pragma unroll
            for (int k = 0; k < 8; k++) {
                int mism = __popcll(win ^ sW2[k]);          // sum = 36 - 2*mism
                m8[k] |= (((uint32_t)(18 - mism)) >> 31) << pos;  // mism > 18
                z8[k] |= (uint32_t)(mism != 18) << pos;
            }
        }
    }
    // assemble 72-bit pairs, bit idx = k*9 + pos (filter-major, conv3 layout)
    unsigned long long b2lo = 0, nzlo = 0;
#pragma unroll
    for (int k = 0; k < 7; k++) {
        b2lo |= (unsigned long long)m8[k] << (9 * k);
        nzlo |= (unsigned long long)z8[k] << (9 * k);
    }
    b2lo |= (unsigned long long)(m8[7] & 1u) << 63;
    nzlo |= (unsigned long long)(z8[7] & 1u) << 63;
    uint32_t b2hi = m8[7] >> 1, nzhi = z8[7] >> 1;

    // ---- conv3: 72 ternary inputs, 16 outputs ----
    int ztot = __popcll(nzlo) + __popc(nzhi);
    uint32_t b3 = 0, nz3 = 0;
#pragma unroll
    for (int j = 0; j < 16; j++) {
        int m = __popcll(nzlo & ~(b2lo ^ sW3lo[j]))
              + __popc((nzhi & ~(b2hi ^ sW3hi[j])) & 0xFF);
        int sum = 2 * m - ztot;
        b3  |= (uint32_t)(sum < 0)  << j;
        nz3 |= (uint32_t)(sum != 0) << j;
    }

    // ---- fc1: 16 ternary inputs, 8 outputs ----
    int z3 = __popc(nz3);
    uint32_t b4 = 0, nz4 = 0;
#pragma unroll
    for (int o = 0; o < 8; o++) {
        int m = __popc((nz3 & ~(b3 ^ sWF1[o])) & 0xFFFF);
        int sum = 2 * m - z3;
        b4  |= (uint32_t)(sum < 0)  << o;
        nz4 |= (uint32_t)(sum != 0) << o;
    }

    // ---- fc2: raw integer sum as float (streaming store) ----
    int m = __popc((nz4 & ~(b4 ^ sWF2)) & 0xFF);
    __stcs(out + s, (float)(2 * m - __popc(nz4)));
}

// ---------------------------------------------------------------------------
// Inputs (metadata order): x, w1, w2, w3, wfc1, wfc2
// ---------------------------------------------------------------------------
extern "C" void kernel_launch(void* const* d_in, const int* in_sizes, int n_in,
                              void* d_out, int out_size)
{
    const float* x    = (const float*)d_in[0];
    const float* w1   = (const float*)d_in[1];
    const float* w2   = (const float*)d_in[2];
    const float* w3   = (const float*)d_in[3];
    const float* wfc1 = (const float*)d_in[4];
    const float* wfc2 = (const float*)d_in[5];
    int n = in_sizes[0] / 225;

    net_kernel<<<(n + 255) / 256, 256>>>(x, w1, w2, w3, wfc1, wfc2,
                                         (float*)d_out, n);
}